// round 1
// baseline (speedup 1.0000x reference)
#include <cuda_runtime.h>

#define M_ROWS 2048
#define NDIM   128
#define NN     (NDIM * NDIM)     // 16384 complex entries of matH
#define NV4    (NN / 4)          // 4096 float4 per component

// Device scratch (allocation-free rule: __device__ globals)
__device__ float g_hre[NN];
__device__ float g_him[NN];
__device__ float g_rowsq[M_ROWS];

// ---------------------------------------------------------------------------
// Kernel 1: build matH from theta/evl. One block of 128 threads (thread t owns
// Hilbert index t). Scalar reductions done serially by thread 0 (128 adds,
// negligible, fully deterministic).
// ---------------------------------------------------------------------------
__global__ __launch_bounds__(128) void prep_kernel(const float* __restrict__ theta,
                                                   const float* __restrict__ evl) {
    __shared__ float e0r[NDIM], e0i[NDIM], e1r[NDIM], e1i[NDIM];
    __shared__ float red[NDIM];
    __shared__ float sc[4];
    const int t = threadIdx.x;

    const float th0 = theta[t];
    const float th1 = theta[NDIM + t];
    const float th2 = theta[2 * NDIM + t];
    const float th3 = theta[3 * NDIM + t];

    // ||c0||
    red[t] = th0 * th0 + th1 * th1;
    __syncthreads();
    if (t == 0) { float s = 0.f; for (int i = 0; i < NDIM; i++) s += red[i]; sc[0] = rsqrtf(s); }
    __syncthreads();
    const float inv0 = sc[0];
    const float a0 = th0 * inv0, b0 = th1 * inv0;   // evc0 = a0 + i b0
    e0r[t] = a0; e0i[t] = b0;

    // vdot(evc0, c1) = sum conj(evc0)*c1
    red[t] = a0 * th2 + b0 * th3;
    __syncthreads();
    if (t == 0) { float s = 0.f; for (int i = 0; i < NDIM; i++) s += red[i]; sc[1] = s; }
    __syncthreads();
    red[t] = a0 * th3 - b0 * th2;
    __syncthreads();
    if (t == 0) { float s = 0.f; for (int i = 0; i < NDIM; i++) s += red[i]; sc[2] = s; }
    __syncthreads();
    const float dr = sc[1], di = sc[2];

    // c1 -= vdot * evc0 ; normalize
    const float c1r = th2 - (dr * a0 - di * b0);
    const float c1i = th3 - (dr * b0 + di * a0);
    red[t] = c1r * c1r + c1i * c1i;
    __syncthreads();
    if (t == 0) {
        float s = 0.f; for (int i = 0; i < NDIM; i++) s += red[i];
        sc[3] = rsqrtf(s);
        // eigenvalues: softplus then L2-normalize
        const float l0 = log1pf(expf(evl[0]));
        const float l1 = log1pf(expf(evl[1]));
        const float nl = rsqrtf(l0 * l0 + l1 * l1);
        sc[0] = l0 * nl;   // lam0 (sc[0]/sc[1] safely reusable: inv0/dr already consumed)
        sc[1] = l1 * nl;   // lam1
    }
    __syncthreads();
    const float inv1 = sc[3];
    e1r[t] = c1r * inv1; e1i[t] = c1i * inv1;
    __syncthreads();
    const float lam0 = sc[0], lam1 = sc[1];

    // matH[i][j] = lam0*evc0[i]*conj(evc0[j]) - lam1*evc1[i]*conj(evc1[j])
    const float A0 = e0r[t], B0 = e0i[t], A1 = e1r[t], B1 = e1i[t];
    #pragma unroll 4
    for (int j = 0; j < NDIM; j++) {
        const float aj0 = e0r[j], bj0 = e0i[j], aj1 = e1r[j], bj1 = e1i[j];
        g_hre[t * NDIM + j] = lam0 * (A0 * aj0 + B0 * bj0) - lam1 * (A1 * aj1 + B1 * bj1);
        g_him[t * NDIM + j] = lam0 * (B0 * aj0 - A0 * bj0) - lam1 * (B1 * aj1 - A1 * bj1);
    }
}

// ---------------------------------------------------------------------------
// Kernel 2: the 256 MB streaming matvec. One warp per row; h staged in 128 KB
// of shared memory per block (read from L2 once per block, not once per row).
// v = (re - i*im) . (hre + i*him):
//   vr = sum re*hre + im*him ;  vi = sum re*him - im*hre
// ---------------------------------------------------------------------------
__global__ __launch_bounds__(512) void dot_kernel(const float* __restrict__ bre,
                                                  const float* __restrict__ bim) {
    extern __shared__ float4 sh4[];          // 8192 float4 = 128 KB
    float4* shre = sh4;
    float4* shim = sh4 + NV4;

    const float4* ghre = (const float4*)g_hre;
    const float4* ghim = (const float4*)g_him;
    for (int i = threadIdx.x; i < NV4; i += 512) {
        shre[i] = ghre[i];
        shim[i] = ghim[i];
    }
    __syncthreads();

    const int warp = threadIdx.x >> 5;
    const int lane = threadIdx.x & 31;

    for (int row = warp * gridDim.x + blockIdx.x; row < M_ROWS; row += 16 * gridDim.x) {
        const float4* br = (const float4*)bre + (size_t)row * NV4;
        const float4* bi = (const float4*)bim + (size_t)row * NV4;
        float vr = 0.f, vi = 0.f;
        #pragma unroll 4
        for (int c = lane; c < NV4; c += 32) {
            const float4 r  = br[c];
            const float4 m  = bi[c];
            const float4 hr = shre[c];
            const float4 hi = shim[c];
            vr += r.x * hr.x + m.x * hi.x;
            vi += r.x * hi.x - m.x * hr.x;
            vr += r.y * hr.y + m.y * hi.y;
            vi += r.y * hi.y - m.y * hr.y;
            vr += r.z * hr.z + m.z * hi.z;
            vi += r.z * hi.z - m.z * hr.z;
            vr += r.w * hr.w + m.w * hi.w;
            vi += r.w * hi.w - m.w * hr.w;
        }
        #pragma unroll
        for (int o = 16; o; o >>= 1) {
            vr += __shfl_xor_sync(0xffffffffu, vr, o);
            vi += __shfl_xor_sync(0xffffffffu, vi, o);
        }
        if (lane == 0) g_rowsq[row] = vr * vr + vi * vi;
    }
}

// ---------------------------------------------------------------------------
// Kernel 3: deterministic final reduction of 2048 per-row squared magnitudes.
// ---------------------------------------------------------------------------
__global__ __launch_bounds__(256) void reduce_kernel(float* __restrict__ out) {
    __shared__ float red[256];
    const int t = threadIdx.x;
    float s = 0.f;
    for (int i = t; i < M_ROWS; i += 256) s += g_rowsq[i];
    red[t] = s;
    __syncthreads();
    for (int o = 128; o; o >>= 1) {
        if (t < o) red[t] += red[t + o];
        __syncthreads();
    }
    if (t == 0) out[0] = red[0];
}

// ---------------------------------------------------------------------------
extern "C" void kernel_launch(void* const* d_in, const int* in_sizes, int n_in,
                              void* d_out, int out_size) {
    const float* bre   = (const float*)d_in[0];
    const float* bim   = (const float*)d_in[1];
    const float* theta = (const float*)d_in[2];
    const float* evl   = (const float*)d_in[3];

    int sms = 148;
    cudaDeviceGetAttribute(&sms, cudaDevAttrMultiProcessorCount, 0);

    // 128 KB dynamic smem > 48 KB default: opt in (idempotent, called every time)
    cudaFuncSetAttribute(dot_kernel, cudaFuncAttributeMaxDynamicSharedMemorySize,
                         2 * NV4 * (int)sizeof(float4));

    prep_kernel<<<1, 128>>>(theta, evl);
    dot_kernel<<<sms, 512, 2 * NV4 * (int)sizeof(float4)>>>(bre, bim);
    reduce_kernel<<<1, 256>>>((float*)d_out);
}

// round 2
// speedup vs baseline: 1.8526x; 1.8526x over previous
#include <cuda_runtime.h>

#define M_ROWS  2048
#define NDIM    128
#define NN      (NDIM * NDIM)      // 16384 complex entries of matH
#define NV4     (NN / 4)           // 4096 float4 per row per component
#define HV4     (NV4 / 2)          // 2048 float4 per half-row
#define NTASK   (2 * M_ROWS)       // 4096 half-row tasks
#define THREADS 1024

// Device scratch (allocation-free rule: __device__ globals)
__device__ float    g_pr[NTASK];
__device__ float    g_pi[NTASK];
__device__ unsigned g_ctr = 0;

// ---------------------------------------------------------------------------
// One fused kernel:
//  phase A: every block redundantly builds matH in its own 128 KB smem
//  phase B: warp-per-half-row streaming dot (256 MB read once)
//  phase C: last-arriving block does the deterministic final reduction
// ---------------------------------------------------------------------------
__global__ __launch_bounds__(THREADS) void fused_kernel(
    const float* __restrict__ bre, const float* __restrict__ bim,
    const float* __restrict__ theta, const float* __restrict__ evl,
    float* __restrict__ out)
{
    extern __shared__ float sh[];             // 2 * NN floats = 128 KB
    float* hre = sh;
    float* him = sh + NN;

    __shared__ float e0r[NDIM], e0i[NDIM], e1r[NDIM], e1i[NDIM];
    __shared__ float wred[32];
    __shared__ float sc[6];
    __shared__ unsigned slast;

    const int tid  = threadIdx.x;
    const int lane = tid & 31;
    const int warp = tid >> 5;

    // ---------------- phase A: matH construction ----------------
    float th0 = 0.f, th1 = 0.f, th2 = 0.f, th3 = 0.f;
    if (tid < NDIM) {
        th0 = theta[tid];
        th1 = theta[NDIM + tid];
        th2 = theta[2 * NDIM + tid];
        th3 = theta[3 * NDIM + tid];
    }

    // deterministic block reduction: shuffle within warp, thread0 sums 32
    // partials in fixed order (idle warps contribute exact zeros)
    auto blockReduce = [&](float v, int slot) -> float {
        #pragma unroll
        for (int o = 16; o; o >>= 1) v += __shfl_xor_sync(0xffffffffu, v, o);
        if (lane == 0) wred[warp] = v;
        __syncthreads();
        if (tid == 0) {
            float s = 0.f;
            #pragma unroll
            for (int i = 0; i < 32; i++) s += wred[i];
            sc[slot] = s;
        }
        __syncthreads();
        return sc[slot];
    };

    const float s0   = blockReduce(th0 * th0 + th1 * th1, 0);
    const float inv0 = rsqrtf(s0);
    const float a0 = th0 * inv0, b0 = th1 * inv0;          // evc0
    const float dr = blockReduce(a0 * th2 + b0 * th3, 1);  // Re vdot(evc0,c1)
    const float di = blockReduce(a0 * th3 - b0 * th2, 2);  // Im vdot(evc0,c1)
    const float c1r = th2 - (dr * a0 - di * b0);
    const float c1i = th3 - (dr * b0 + di * a0);
    const float s1   = blockReduce(c1r * c1r + c1i * c1i, 3);
    const float inv1 = rsqrtf(s1);

    if (tid < NDIM) {
        e0r[tid] = a0;        e0i[tid] = b0;
        e1r[tid] = c1r * inv1; e1i[tid] = c1i * inv1;
    }
    if (tid == 0) {
        const float l0 = log1pf(expf(evl[0]));
        const float l1 = log1pf(expf(evl[1]));
        const float nl = rsqrtf(l0 * l0 + l1 * l1);
        sc[4] = l0 * nl;                                    // lam0
        sc[5] = l1 * nl;                                    // lam1
    }
    __syncthreads();
    const float lam0 = sc[4], lam1 = sc[5];

    // h[i*128+j] = lam0*evc0[i]*conj(evc0[j]) - lam1*evc1[i]*conj(evc1[j])
    #pragma unroll
    for (int k = 0; k < NN / THREADS; k++) {
        const int c = tid + k * THREADS;                    // stride-1: no conflicts
        const int i = c >> 7, j = c & (NDIM - 1);
        const float A0 = e0r[i], B0 = e0i[i], A1 = e1r[i], B1 = e1i[i];
        const float aj0 = e0r[j], bj0 = e0i[j], aj1 = e1r[j], bj1 = e1i[j];
        hre[c] = lam0 * (A0 * aj0 + B0 * bj0) - lam1 * (A1 * aj1 + B1 * bj1);
        him[c] = lam0 * (B0 * aj0 - A0 * bj0) - lam1 * (B1 * aj1 - A1 * bj1);
    }
    __syncthreads();

    // ---------------- phase B: streaming half-row dots ----------------
    // v = (re - i*im) . (hre + i*him):
    //   vr += re*hre + im*him ;  vi += re*him - im*hre
    const float4* hre4 = (const float4*)hre;
    const float4* him4 = (const float4*)him;
    const int nwarps = (THREADS / 32) * gridDim.x;

    for (int task = warp * gridDim.x + blockIdx.x; task < NTASK; task += nwarps) {
        const int row = task & (M_ROWS - 1);
        const int cb  = (task >> 11) * HV4;                 // 0 or HV4
        const float4* br = (const float4*)bre + (size_t)row * NV4 + cb;
        const float4* bi = (const float4*)bim + (size_t)row * NV4 + cb;

        float vr = 0.f, vi = 0.f;
        #pragma unroll 1
        for (int c = lane; c < HV4; c += 128) {             // 16 iterations
            const float4 r0 = __ldcs(br + c);
            const float4 r1 = __ldcs(br + c + 32);
            const float4 r2 = __ldcs(br + c + 64);
            const float4 r3 = __ldcs(br + c + 96);
            const float4 m0 = __ldcs(bi + c);
            const float4 m1 = __ldcs(bi + c + 32);
            const float4 m2 = __ldcs(bi + c + 64);
            const float4 m3 = __ldcs(bi + c + 96);

            float4 h, g;
            h = hre4[cb + c];      g = him4[cb + c];
            vr += r0.x*h.x + m0.x*g.x;  vi += r0.x*g.x - m0.x*h.x;
            vr += r0.y*h.y + m0.y*g.y;  vi += r0.y*g.y - m0.y*h.y;
            vr += r0.z*h.z + m0.z*g.z;  vi += r0.z*g.z - m0.z*h.z;
            vr += r0.w*h.w + m0.w*g.w;  vi += r0.w*g.w - m0.w*h.w;
            h = hre4[cb + c + 32]; g = him4[cb + c + 32];
            vr += r1.x*h.x + m1.x*g.x;  vi += r1.x*g.x - m1.x*h.x;
            vr += r1.y*h.y + m1.y*g.y;  vi += r1.y*g.y - m1.y*h.y;
            vr += r1.z*h.z + m1.z*g.z;  vi += r1.z*g.z - m1.z*h.z;
            vr += r1.w*h.w + m1.w*g.w;  vi += r1.w*g.w - m1.w*h.w;
            h = hre4[cb + c + 64]; g = him4[cb + c + 64];
            vr += r2.x*h.x + m2.x*g.x;  vi += r2.x*g.x - m2.x*h.x;
            vr += r2.y*h.y + m2.y*g.y;  vi += r2.y*g.y - m2.y*h.y;
            vr += r2.z*h.z + m2.z*g.z;  vi += r2.z*g.z - m2.z*h.z;
            vr += r2.w*h.w + m2.w*g.w;  vi += r2.w*g.w - m2.w*h.w;
            h = hre4[cb + c + 96]; g = him4[cb + c + 96];
            vr += r3.x*h.x + m3.x*g.x;  vi += r3.x*g.x - m3.x*h.x;
            vr += r3.y*h.y + m3.y*g.y;  vi += r3.y*g.y - m3.y*h.y;
            vr += r3.z*h.z + m3.z*g.z;  vi += r3.z*g.z - m3.z*h.z;
            vr += r3.w*h.w + m3.w*g.w;  vi += r3.w*g.w - m3.w*h.w;
        }
        #pragma unroll
        for (int o = 16; o; o >>= 1) {
            vr += __shfl_xor_sync(0xffffffffu, vr, o);
            vi += __shfl_xor_sync(0xffffffffu, vi, o);
        }
        if (lane == 0) { g_pr[task] = vr; g_pi[task] = vi; }
    }

    // ---------------- phase C: last block reduces ----------------
    __syncthreads();
    if (tid == 0) {
        __threadfence();
        const unsigned old = atomicAdd(&g_ctr, 1u);
        slast = (old == gridDim.x - 1) ? 1u : 0u;
        if (slast) g_ctr = 0;                               // reset for next replay
    }
    __syncthreads();

    if (slast) {
        float acc = 0.f;
        for (int r = tid; r < M_ROWS; r += THREADS) {       // 2 rows per thread
            const float vr = __ldcg(&g_pr[r]) + __ldcg(&g_pr[r + M_ROWS]);
            const float vi = __ldcg(&g_pi[r]) + __ldcg(&g_pi[r + M_ROWS]);
            acc += vr * vr + vi * vi;
        }
        #pragma unroll
        for (int o = 16; o; o >>= 1) acc += __shfl_xor_sync(0xffffffffu, acc, o);
        if (lane == 0) wred[warp] = acc;
        __syncthreads();
        if (warp == 0) {
            float v = wred[lane];
            #pragma unroll
            for (int o = 16; o; o >>= 1) v += __shfl_xor_sync(0xffffffffu, v, o);
            if (lane == 0) out[0] = v;
        }
    }
}

// ---------------------------------------------------------------------------
extern "C" void kernel_launch(void* const* d_in, const int* in_sizes, int n_in,
                              void* d_out, int out_size) {
    const float* bre   = (const float*)d_in[0];
    const float* bim   = (const float*)d_in[1];
    const float* theta = (const float*)d_in[2];
    const float* evl   = (const float*)d_in[3];

    int sms = 148;
    cudaDeviceGetAttribute(&sms, cudaDevAttrMultiProcessorCount, 0);

    const int smem = 2 * NN * (int)sizeof(float);           // 128 KB
    cudaFuncSetAttribute(fused_kernel, cudaFuncAttributeMaxDynamicSharedMemorySize, smem);

    fused_kernel<<<sms, THREADS, smem>>>(bre, bim, theta, evl, (float*)d_out);
}